// round 1
// baseline (speedup 1.0000x reference)
#include <cuda_runtime.h>
#include <math.h>

#define Bsz   8
#define C     384
#define NHEAD 12
#define HD    32
#define FF    1536
#define MROWS 32768   // B * H * W = 8*64*64

// ---------------- scratch (device globals; no allocation) ----------------
__device__ float g_ada[Bsz * 2304];
__device__ float g_h[MROWS * C];                     // LN out / proj out / ff2 out
__device__ float g_qkv[(size_t)MROWS * 1152];
__device__ float g_attn[MROWS * C];
__device__ float g_ff1[(size_t)MROWS * FF];

// ---------------- copy x -> out ----------------
__global__ void copy_kernel(float* __restrict__ dst, const float* __restrict__ src, int n) {
    int i = blockIdx.x * blockDim.x + threadIdx.x;
    if (i < n) dst[i] = src[i];
}

// ---------------- adaLN: ada[b,:] = silu(emb[b]) @ ada_w.T + ada_b ----------------
__global__ void ada_kernel(const float* __restrict__ emb, const float* __restrict__ ada_w,
                           const float* __restrict__ ada_b, float* __restrict__ ada_out) {
    int b = blockIdx.y;
    int j = blockIdx.x * blockDim.x + threadIdx.x;   // 0..2303
    __shared__ float se[C];
    for (int k = threadIdx.x; k < C; k += blockDim.x) {
        float e = emb[b * C + k];
        se[k] = e / (1.0f + __expf(-e));
    }
    __syncthreads();
    const float* wrow = ada_w + (size_t)j * C;
    float s = ada_b[j];
#pragma unroll 4
    for (int k = 0; k < C; k++) s += se[k] * wrow[k];
    ada_out[b * 2304 + j] = s;
}

// ---------------- LayerNorm + modulate (+ optional window/shift gather) ----------------
// windowed=1: output row wrow is (win,n) layout; source row is spatial with shift gather.
__global__ void ln_mod_kernel(const float* __restrict__ x, const float* __restrict__ ada,
                              float* __restrict__ out, int shift, int windowed,
                              int sc_off, int sh_off) {
    int wrow = blockIdx.x;      // 0..32767
    int tid = threadIdx.x;      // 128 threads
    int b, srcrow;
    if (windowed) {
        int win = wrow >> 6, n = wrow & 63;
        b = win >> 6;
        int widx = win & 63;
        int wh = widx >> 3, wwi = widx & 7, ii = n >> 3, jj = n & 7;
        int r = (wh * 8 + ii + shift) & 63;
        int cc = (wwi * 8 + jj + shift) & 63;
        srcrow = b * 4096 + r * 64 + cc;
    } else {
        b = wrow >> 12;
        srcrow = wrow;
    }
    const float* xr = x + (size_t)srcrow * C;
    float v0 = xr[tid], v1 = xr[tid + 128], v2 = xr[tid + 256];
    float s = v0 + v1 + v2;
    float q = v0 * v0 + v1 * v1 + v2 * v2;
#pragma unroll
    for (int o = 16; o > 0; o >>= 1) {
        s += __shfl_down_sync(0xffffffffu, s, o);
        q += __shfl_down_sync(0xffffffffu, q, o);
    }
    __shared__ float rs[4], rq[4], mv[2];
    int wid = tid >> 5, lane = tid & 31;
    if (lane == 0) { rs[wid] = s; rq[wid] = q; }
    __syncthreads();
    if (tid == 0) {
        float S = rs[0] + rs[1] + rs[2] + rs[3];
        float Q = rq[0] + rq[1] + rq[2] + rq[3];
        float mean = S * (1.0f / C);
        float var = Q * (1.0f / C) - mean * mean;
        mv[0] = mean;
        mv[1] = rsqrtf(var + 1e-6f);
    }
    __syncthreads();
    float mean = mv[0], rstd = mv[1];
    const float* sc = ada + b * 2304 + sc_off;
    const float* sh = ada + b * 2304 + sh_off;
    float* orow = out + (size_t)wrow * C;
    orow[tid]       = (v0 - mean) * rstd * (1.0f + sc[tid])       + sh[tid];
    orow[tid + 128] = (v1 - mean) * rstd * (1.0f + sc[tid + 128]) + sh[tid + 128];
    orow[tid + 256] = (v2 - mean) * rstd * (1.0f + sc[tid + 256]) + sh[tid + 256];
}

// ---------------- generic GEMM: C[m,n] = sum_k A[m,k] * W[n,k] + bias[n]; act=1 -> exact GELU ----------------
#define BM 64
#define BN 64
#define BK 16
__global__ __launch_bounds__(256) void gemm_nt(const float* __restrict__ A,
                                               const float* __restrict__ W,
                                               const float* __restrict__ bias,
                                               float* __restrict__ Cout,
                                               int N, int K, int act) {
    __shared__ float As[BK][BM + 4];   // row stride 68 floats = 272B (16B aligned)
    __shared__ float Bs[BK][BN + 4];
    int tid = threadIdx.x;
    int m0 = blockIdx.y * BM, n0 = blockIdx.x * BN;
    int tm = tid >> 4, tn = tid & 15;
    int lrow = tid >> 2, lk = (tid & 3) * 4;
    float acc[4][4] = {};
    for (int k0 = 0; k0 < K; k0 += BK) {
        float4 a = *(const float4*)&A[(size_t)(m0 + lrow) * K + k0 + lk];
        As[lk + 0][lrow] = a.x; As[lk + 1][lrow] = a.y;
        As[lk + 2][lrow] = a.z; As[lk + 3][lrow] = a.w;
        float4 bv = *(const float4*)&W[(size_t)(n0 + lrow) * K + k0 + lk];
        Bs[lk + 0][lrow] = bv.x; Bs[lk + 1][lrow] = bv.y;
        Bs[lk + 2][lrow] = bv.z; Bs[lk + 3][lrow] = bv.w;
        __syncthreads();
#pragma unroll
        for (int k = 0; k < BK; k++) {
            float4 av = *(float4*)&As[k][tm * 4];
            float4 bb = *(float4*)&Bs[k][tn * 4];
            acc[0][0] += av.x * bb.x; acc[0][1] += av.x * bb.y; acc[0][2] += av.x * bb.z; acc[0][3] += av.x * bb.w;
            acc[1][0] += av.y * bb.x; acc[1][1] += av.y * bb.y; acc[1][2] += av.y * bb.z; acc[1][3] += av.y * bb.w;
            acc[2][0] += av.z * bb.x; acc[2][1] += av.z * bb.y; acc[2][2] += av.z * bb.z; acc[2][3] += av.z * bb.w;
            acc[3][0] += av.w * bb.x; acc[3][1] += av.w * bb.y; acc[3][2] += av.w * bb.z; acc[3][3] += av.w * bb.w;
        }
        __syncthreads();
    }
#pragma unroll
    for (int i = 0; i < 4; i++) {
        int row = m0 + tm * 4 + i;
        int col = n0 + tn * 4;
        float4 r;
        float* pv = &r.x;
#pragma unroll
        for (int j = 0; j < 4; j++) {
            float v = acc[i][j] + bias[col + j];
            if (act == 1) v = 0.5f * v * (1.0f + erff(v * 0.70710678118654752f));
            pv[j] = v;
        }
        *(float4*)&Cout[(size_t)row * N + col] = r;
    }
}

// ---------------- window attention: one block per (window, head), 64 threads ----------------
__device__ __forceinline__ int regid(int r) { return r < 56 ? 0 : (r < 60 ? 1 : 2); }

__global__ __launch_bounds__(64) void attn_kernel(const float* __restrict__ qkv,
                                                  const float* __restrict__ bias_table,
                                                  float* __restrict__ out, int shift) {
    int win = blockIdx.x;    // 0..511
    int head = blockIdx.y;   // 0..11
    int n = threadIdx.x;     // 0..63
    __shared__ float ks[64][HD];
    __shared__ float vs[64][HD];
    size_t base = (size_t)win * 64 * 1152 + head * HD;
    for (int idx = n; idx < 64 * HD; idx += 64) {
        int m = idx >> 5, d = idx & 31;
        ks[m][d] = qkv[base + (size_t)m * 1152 + 384 + d];
        vs[m][d] = qkv[base + (size_t)m * 1152 + 768 + d];
    }
    float q[HD];
#pragma unroll
    for (int d = 0; d < HD; d++) q[d] = qkv[base + (size_t)n * 1152 + d];
    __syncthreads();

    int widx = win & 63;
    int wh = widx >> 3, wwi = widx & 7;
    int ni = n >> 3, nj = n & 7;
    int labn = 0;
    if (shift > 0) labn = regid(wh * 8 + ni) * 3 + regid(wwi * 8 + nj);

    float s[64];
    float mx = -1e30f;
#pragma unroll
    for (int m = 0; m < 64; m++) {
        float acc = 0.0f;
#pragma unroll
        for (int d = 0; d < HD; d++) acc += q[d] * ks[m][d];
        acc *= 0.17677669529663687f;   // 1/sqrt(32)
        int mi = m >> 3, mj = m & 7;
        int rel = (ni - mi + 7) * 15 + (nj - mj + 7);
        acc += bias_table[rel * NHEAD + head];
        if (shift > 0) {
            int labm = regid(wh * 8 + mi) * 3 + regid(wwi * 8 + mj);
            if (labm != labn) acc -= 100.0f;
        }
        s[m] = acc;
        mx = fmaxf(mx, acc);
    }
    float sum = 0.0f;
#pragma unroll
    for (int m = 0; m < 64; m++) { s[m] = __expf(s[m] - mx); sum += s[m]; }
    float inv = 1.0f / sum;
    float o[HD] = {};
#pragma unroll
    for (int m = 0; m < 64; m++) {
        float p = s[m] * inv;
#pragma unroll
        for (int d = 0; d < HD; d++) o[d] += p * vs[m][d];
    }
    float* orow = out + (size_t)(win * 64 + n) * C + head * HD;
#pragma unroll
    for (int d = 0; d < HD; d++) orow[d] = o[d];
}

// ---------------- residual scatter (SA path): x += g_sa * un-window(un-shift(proj_out)) ----------------
__global__ void resid_sa_kernel(float* __restrict__ x, const float* __restrict__ pout,
                                const float* __restrict__ ada, int shift) {
    int idx = blockIdx.x * blockDim.x + threadIdx.x;
    if (idx >= MROWS * C) return;
    int wrow = idx / C, c = idx - wrow * C;
    int win = wrow >> 6, n = wrow & 63;
    int b = win >> 6, widx = win & 63;
    int wh = widx >> 3, wwi = widx & 7, ii = n >> 3, jj = n & 7;
    int r = (wh * 8 + ii + shift) & 63;
    int cc = (wwi * 8 + jj + shift) & 63;
    size_t drow = (size_t)b * 4096 + r * 64 + cc;
    float g = ada[b * 2304 + 768 + c];
    x[drow * C + c] += g * pout[(size_t)wrow * C + c];
}

// ---------------- residual (FF path): x += g_ff * ffout ----------------
__global__ void resid_ff_kernel(float* __restrict__ x, const float* __restrict__ fout,
                                const float* __restrict__ ada) {
    int idx = blockIdx.x * blockDim.x + threadIdx.x;
    if (idx >= MROWS * C) return;
    int row = idx / C, c = idx - row * C;
    int b = row >> 12;
    x[idx] += ada[b * 2304 + 1920 + c] * fout[idx];
}

// ---------------- host ----------------
extern "C" void kernel_launch(void* const* d_in, const int* in_sizes, int n_in,
                              void* d_out, int out_size) {
    const float* x        = (const float*)d_in[0];
    const float* emb      = (const float*)d_in[3];
    const float* qkv_w    = (const float*)d_in[4];
    const float* qkv_b    = (const float*)d_in[5];
    const float* proj_w   = (const float*)d_in[6];
    const float* proj_b   = (const float*)d_in[7];
    const float* ff1_w    = (const float*)d_in[8];
    const float* ff1_b    = (const float*)d_in[9];
    const float* ff2_w    = (const float*)d_in[10];
    const float* ff2_b    = (const float*)d_in[11];
    const float* ada_w    = (const float*)d_in[12];
    const float* ada_b    = (const float*)d_in[13];
    const float* btab     = (const float*)d_in[14];
    float* xo = (float*)d_out;

    float *p_ada, *p_h, *p_qkv, *p_attn, *p_ff1;
    cudaGetSymbolAddress((void**)&p_ada,  g_ada);
    cudaGetSymbolAddress((void**)&p_h,    g_h);
    cudaGetSymbolAddress((void**)&p_qkv,  g_qkv);
    cudaGetSymbolAddress((void**)&p_attn, g_attn);
    cudaGetSymbolAddress((void**)&p_ff1,  g_ff1);

    const int NTOT = MROWS * C;
    copy_kernel<<<(NTOT + 255) / 256, 256>>>(xo, x, NTOT);

    for (int i = 0; i < 2; i++) {
        int shift = (i == 0) ? 0 : 4;
        const float* qw  = qkv_w  + (size_t)i * 1152 * C;
        const float* qb  = qkv_b  + (size_t)i * 1152;
        const float* pw  = proj_w + (size_t)i * C * C;
        const float* pb  = proj_b + (size_t)i * C;
        const float* f1w = ff1_w  + (size_t)i * FF * C;
        const float* f1b = ff1_b  + (size_t)i * FF;
        const float* f2w = ff2_w  + (size_t)i * C * FF;
        const float* f2b = ff2_b  + (size_t)i * C;
        const float* aw  = ada_w  + (size_t)i * 2304 * C;
        const float* ab  = ada_b  + (size_t)i * 2304;
        const float* bt  = btab   + (size_t)i * 225 * NHEAD;

        // adaLN parameters
        ada_kernel<<<dim3(2304 / 256, Bsz), 256>>>(emb, aw, ab, p_ada);
        // LN1 + modulate + window/shift gather
        ln_mod_kernel<<<MROWS, 128>>>(xo, p_ada, p_h, shift, 1, 384, 0);
        // QKV
        gemm_nt<<<dim3(1152 / BN, MROWS / BM), 256>>>(p_h, qw, qb, p_qkv, 1152, C, 0);
        // window attention
        attn_kernel<<<dim3(512, NHEAD), 64>>>(p_qkv, bt, p_attn, shift);
        // proj
        gemm_nt<<<dim3(C / BN, MROWS / BM), 256>>>(p_attn, pw, pb, p_h, C, C, 0);
        // residual (scatter through inverse window/shift)
        resid_sa_kernel<<<(NTOT + 255) / 256, 256>>>(xo, p_h, p_ada, shift);
        // LN2 + modulate
        ln_mod_kernel<<<MROWS, 128>>>(xo, p_ada, p_h, 0, 0, 1536, 1152);
        // FF1 + exact GELU
        gemm_nt<<<dim3(FF / BN, MROWS / BM), 256>>>(p_h, f1w, f1b, p_ff1, FF, C, 1);
        // FF2
        gemm_nt<<<dim3(C / BN, MROWS / BM), 256>>>(p_ff1, f2w, f2b, p_h, C, FF, 0);
        // residual
        resid_ff_kernel<<<(NTOT + 255) / 256, 256>>>(xo, p_h, p_ada);
    }
}

// round 5
// speedup vs baseline: 2.5132x; 2.5132x over previous
#include <cuda_runtime.h>
#include <cstdint>
#include <math.h>

#define Bsz   8
#define C     384
#define NHEAD 12
#define HD    32
#define FF    1536
#define MROWS 32768   // B * H * W = 8*64*64

// ---------------- scratch (device globals; no allocation) ----------------
__device__ float g_ada[Bsz * 2304];
__device__ float g_h[MROWS * C];
__device__ float g_qkv[(size_t)MROWS * 1152];
__device__ float g_attn[MROWS * C];
__device__ float g_ff1[(size_t)MROWS * FF];

// ---------------- copy x -> out ----------------
__global__ void copy_kernel(float* __restrict__ dst, const float* __restrict__ src, int n) {
    int i = blockIdx.x * blockDim.x + threadIdx.x;
    if (i < n) dst[i] = src[i];
}

// ---------------- adaLN ----------------
__global__ void ada_kernel(const float* __restrict__ emb, const float* __restrict__ ada_w,
                           const float* __restrict__ ada_b, float* __restrict__ ada_out) {
    int b = blockIdx.y;
    int j = blockIdx.x * blockDim.x + threadIdx.x;
    __shared__ float se[C];
    for (int k = threadIdx.x; k < C; k += blockDim.x) {
        float e = emb[b * C + k];
        se[k] = e / (1.0f + __expf(-e));
    }
    __syncthreads();
    const float* wrow = ada_w + (size_t)j * C;
    float s = ada_b[j];
#pragma unroll 4
    for (int k = 0; k < C; k++) s += se[k] * wrow[k];
    ada_out[b * 2304 + j] = s;
}

// ---------------- LayerNorm + modulate (+ optional window/shift gather) ----------------
__global__ void ln_mod_kernel(const float* __restrict__ x, const float* __restrict__ ada,
                              float* __restrict__ out, int shift, int windowed,
                              int sc_off, int sh_off) {
    int wrow = blockIdx.x;
    int tid = threadIdx.x;
    int b, srcrow;
    if (windowed) {
        int win = wrow >> 6, n = wrow & 63;
        b = win >> 6;
        int widx = win & 63;
        int wh = widx >> 3, wwi = widx & 7, ii = n >> 3, jj = n & 7;
        int r = (wh * 8 + ii + shift) & 63;
        int cc = (wwi * 8 + jj + shift) & 63;
        srcrow = b * 4096 + r * 64 + cc;
    } else {
        b = wrow >> 12;
        srcrow = wrow;
    }
    const float* xr = x + (size_t)srcrow * C;
    float v0 = xr[tid], v1 = xr[tid + 128], v2 = xr[tid + 256];
    float s = v0 + v1 + v2;
    float q = v0 * v0 + v1 * v1 + v2 * v2;
#pragma unroll
    for (int o = 16; o > 0; o >>= 1) {
        s += __shfl_down_sync(0xffffffffu, s, o);
        q += __shfl_down_sync(0xffffffffu, q, o);
    }
    __shared__ float rs[4], rq[4], mv[2];
    int wid = tid >> 5, lane = tid & 31;
    if (lane == 0) { rs[wid] = s; rq[wid] = q; }
    __syncthreads();
    if (tid == 0) {
        float S = rs[0] + rs[1] + rs[2] + rs[3];
        float Q = rq[0] + rq[1] + rq[2] + rq[3];
        float mean = S * (1.0f / C);
        float var = Q * (1.0f / C) - mean * mean;
        mv[0] = mean;
        mv[1] = rsqrtf(var + 1e-6f);
    }
    __syncthreads();
    float mean = mv[0], rstd = mv[1];
    const float* sc = ada + b * 2304 + sc_off;
    const float* sh = ada + b * 2304 + sh_off;
    float* orow = out + (size_t)wrow * C;
    orow[tid]       = (v0 - mean) * rstd * (1.0f + sc[tid])       + sh[tid];
    orow[tid + 128] = (v1 - mean) * rstd * (1.0f + sc[tid + 128]) + sh[tid + 128];
    orow[tid + 256] = (v2 - mean) * rstd * (1.0f + sc[tid + 256]) + sh[tid + 256];
}

// ---------------- tf32 tensor-core GEMM: C[m,n] = sum_k A[m,k]*W[n,k] + bias[n]; act=1 -> GELU ----------------
// Block tile 128x128, BK=16, 8 warps (2x4), warp tile 64x32, mma.m16n8k8.tf32.
// Smem row stride = 20 floats (20 mod 32 coprime pattern -> conflict-free fragment LDS).
#define TSTRIDE 20

__device__ __forceinline__ void cpasync16(uint32_t dst, const float* src) {
    asm volatile("cp.async.cg.shared.global [%0], [%1], 16;" :: "r"(dst), "l"(src));
}
__device__ __forceinline__ void cp_commit() { asm volatile("cp.async.commit_group;"); }
__device__ __forceinline__ void cp_wait0() { asm volatile("cp.async.wait_group 0;"); }

__device__ __forceinline__ void mma_tf32(float* d, const uint32_t* a, const uint32_t* b) {
    asm volatile(
        "mma.sync.aligned.m16n8k8.row.col.f32.tf32.tf32.f32 "
        "{%0,%1,%2,%3}, {%4,%5,%6,%7}, {%8,%9}, {%0,%1,%2,%3};"
        : "+f"(d[0]), "+f"(d[1]), "+f"(d[2]), "+f"(d[3])
        : "r"(a[0]), "r"(a[1]), "r"(a[2]), "r"(a[3]), "r"(b[0]), "r"(b[1]));
}

__global__ __launch_bounds__(256, 2) void gemm_tf32(const float* __restrict__ A,
                                                    const float* __restrict__ W,
                                                    const float* __restrict__ bias,
                                                    float* __restrict__ Cout,
                                                    int N, int K, int act) {
    __shared__ float As[2][128 * TSTRIDE];
    __shared__ float Bs[2][128 * TSTRIDE];

    int tid = threadIdx.x;
    int warp = tid >> 5, lane = tid & 31;
    int grp = lane >> 2, qid = lane & 3;
    int wm = warp >> 2, wn = warp & 3;         // 2 x 4 warp grid
    int m_w = wm * 64, n_w = wn * 32;
    int bm = blockIdx.y * 128, bn = blockIdx.x * 128;

    // cp.async chunk mapping: 512 16B-chunks per tile, 2 per thread
    int ch0 = tid, ch1 = tid + 256;
    int am0 = ch0 >> 2, aq0 = ch0 & 3;
    int am1 = ch1 >> 2, aq1 = ch1 & 3;

    uint32_t sA = (uint32_t)__cvta_generic_to_shared(&As[0][0]);
    uint32_t sB = (uint32_t)__cvta_generic_to_shared(&Bs[0][0]);
    const uint32_t bufBytes = 128 * TSTRIDE * 4;

    float acc[4][4][4];
#pragma unroll
    for (int i = 0; i < 4; i++)
#pragma unroll
        for (int j = 0; j < 4; j++)
#pragma unroll
            for (int r = 0; r < 4; r++) acc[i][j][r] = 0.0f;

    int ntiles = K / 16;
    // prefetch tile 0
    {
        const float* Ab = A + (size_t)(bm + am0) * K + 4 * aq0;
        const float* Ab1 = A + (size_t)(bm + am1) * K + 4 * aq1;
        const float* Wb = W + (size_t)(bn + am0) * K + 4 * aq0;
        const float* Wb1 = W + (size_t)(bn + am1) * K + 4 * aq1;
        cpasync16(sA + (am0 * TSTRIDE + 4 * aq0) * 4, Ab);
        cpasync16(sA + (am1 * TSTRIDE + 4 * aq1) * 4, Ab1);
        cpasync16(sB + (am0 * TSTRIDE + 4 * aq0) * 4, Wb);
        cpasync16(sB + (am1 * TSTRIDE + 4 * aq1) * 4, Wb1);
        cp_commit();
    }

    for (int kt = 0; kt < ntiles; kt++) {
        cp_wait0();
        __syncthreads();
        if (kt + 1 < ntiles) {
            int k0 = (kt + 1) * 16;
            uint32_t dA = sA + ((kt + 1) & 1) * bufBytes;
            uint32_t dB = sB + ((kt + 1) & 1) * bufBytes;
            cpasync16(dA + (am0 * TSTRIDE + 4 * aq0) * 4, A + (size_t)(bm + am0) * K + k0 + 4 * aq0);
            cpasync16(dA + (am1 * TSTRIDE + 4 * aq1) * 4, A + (size_t)(bm + am1) * K + k0 + 4 * aq1);
            cpasync16(dB + (am0 * TSTRIDE + 4 * aq0) * 4, W + (size_t)(bn + am0) * K + k0 + 4 * aq0);
            cpasync16(dB + (am1 * TSTRIDE + 4 * aq1) * 4, W + (size_t)(bn + am1) * K + k0 + 4 * aq1);
            cp_commit();
        }
        const uint32_t* Au = (const uint32_t*)&As[kt & 1][0];
        const uint32_t* Bu = (const uint32_t*)&Bs[kt & 1][0];
#pragma unroll
        for (int kk = 0; kk < 16; kk += 8) {
            uint32_t af[4][4], bf[4][2];
#pragma unroll
            for (int i = 0; i < 4; i++) {
                int m = m_w + 16 * i + grp;
                af[i][0] = Au[m * TSTRIDE + kk + qid];
                af[i][1] = Au[(m + 8) * TSTRIDE + kk + qid];
                af[i][2] = Au[m * TSTRIDE + kk + qid + 4];
                af[i][3] = Au[(m + 8) * TSTRIDE + kk + qid + 4];
            }
#pragma unroll
            for (int j = 0; j < 4; j++) {
                int n = n_w + 8 * j + grp;
                bf[j][0] = Bu[n * TSTRIDE + kk + qid];
                bf[j][1] = Bu[n * TSTRIDE + kk + qid + 4];
            }
#pragma unroll
            for (int i = 0; i < 4; i++)
#pragma unroll
                for (int j = 0; j < 4; j++) mma_tf32(acc[i][j], af[i], bf[j]);
        }
        __syncthreads();
    }

    // epilogue
#pragma unroll
    for (int i = 0; i < 4; i++) {
#pragma unroll
        for (int j = 0; j < 4; j++) {
            int row = bm + m_w + 16 * i + grp;
            int col = bn + n_w + 8 * j + 2 * qid;
            float b0 = __ldg(&bias[col]), b1 = __ldg(&bias[col + 1]);
            float v0 = acc[i][j][0] + b0, v1 = acc[i][j][1] + b1;
            float v2 = acc[i][j][2] + b0, v3 = acc[i][j][3] + b1;
            if (act == 1) {
                v0 = 0.5f * v0 * (1.0f + erff(v0 * 0.70710678118654752f));
                v1 = 0.5f * v1 * (1.0f + erff(v1 * 0.70710678118654752f));
                v2 = 0.5f * v2 * (1.0f + erff(v2 * 0.70710678118654752f));
                v3 = 0.5f * v3 * (1.0f + erff(v3 * 0.70710678118654752f));
            }
            *(float2*)&Cout[(size_t)row * N + col] = make_float2(v0, v1);
            *(float2*)&Cout[(size_t)(row + 8) * N + col] = make_float2(v2, v3);
        }
    }
}

// ---------------- window attention ----------------
__device__ __forceinline__ int regid(int r) { return r < 56 ? 0 : (r < 60 ? 1 : 2); }

__global__ __launch_bounds__(64) void attn_kernel(const float* __restrict__ qkv,
                                                  const float* __restrict__ bias_table,
                                                  float* __restrict__ out, int shift) {
    int win = blockIdx.x;
    int head = blockIdx.y;
    int n = threadIdx.x;
    __shared__ float ks[64][HD];
    __shared__ float vs[64][HD];
    size_t base = (size_t)win * 64 * 1152 + head * HD;
    for (int idx = n; idx < 64 * HD; idx += 64) {
        int m = idx >> 5, d = idx & 31;
        ks[m][d] = qkv[base + (size_t)m * 1152 + 384 + d];
        vs[m][d] = qkv[base + (size_t)m * 1152 + 768 + d];
    }
    float q[HD];
#pragma unroll
    for (int d = 0; d < HD; d++) q[d] = qkv[base + (size_t)n * 1152 + d];
    __syncthreads();

    int widx = win & 63;
    int wh = widx >> 3, wwi = widx & 7;
    int ni = n >> 3, nj = n & 7;
    int labn = 0;
    if (shift > 0) labn = regid(wh * 8 + ni) * 3 + regid(wwi * 8 + nj);

    float s[64];
    float mx = -1e30f;
#pragma unroll
    for (int m = 0; m < 64; m++) {
        float acc = 0.0f;
#pragma unroll
        for (int d = 0; d < HD; d++) acc += q[d] * ks[m][d];
        acc *= 0.17677669529663687f;
        int mi = m >> 3, mj = m & 7;
        int rel = (ni - mi + 7) * 15 + (nj - mj + 7);
        acc += bias_table[rel * NHEAD + head];
        if (shift > 0) {
            int labm = regid(wh * 8 + mi) * 3 + regid(wwi * 8 + mj);
            if (labm != labn) acc -= 100.0f;
        }
        s[m] = acc;
        mx = fmaxf(mx, acc);
    }
    float sum = 0.0f;
#pragma unroll
    for (int m = 0; m < 64; m++) { s[m] = __expf(s[m] - mx); sum += s[m]; }
    float inv = 1.0f / sum;
    float o[HD] = {};
#pragma unroll
    for (int m = 0; m < 64; m++) {
        float p = s[m] * inv;
#pragma unroll
        for (int d = 0; d < HD; d++) o[d] += p * vs[m][d];
    }
    float* orow = out + (size_t)(win * 64 + n) * C + head * HD;
#pragma unroll
    for (int d = 0; d < HD; d++) orow[d] = o[d];
}

// ---------------- residual scatter (SA path) ----------------
__global__ void resid_sa_kernel(float* __restrict__ x, const float* __restrict__ pout,
                                const float* __restrict__ ada, int shift) {
    int idx = blockIdx.x * blockDim.x + threadIdx.x;
    if (idx >= MROWS * C) return;
    int wrow = idx / C, c = idx - wrow * C;
    int win = wrow >> 6, n = wrow & 63;
    int b = win >> 6, widx = win & 63;
    int wh = widx >> 3, wwi = widx & 7, ii = n >> 3, jj = n & 7;
    int r = (wh * 8 + ii + shift) & 63;
    int cc = (wwi * 8 + jj + shift) & 63;
    size_t drow = (size_t)b * 4096 + r * 64 + cc;
    float g = ada[b * 2304 + 768 + c];
    x[drow * C + c] += g * pout[(size_t)wrow * C + c];
}

// ---------------- residual (FF path) ----------------
__global__ void resid_ff_kernel(float* __restrict__ x, const float* __restrict__ fout,
                                const float* __restrict__ ada) {
    int idx = blockIdx.x * blockDim.x + threadIdx.x;
    if (idx >= MROWS * C) return;
    int row = idx / C, c = idx - row * C;
    int b = row >> 12;
    x[idx] += ada[b * 2304 + 1920 + c] * fout[idx];
}

// ---------------- host ----------------
extern "C" void kernel_launch(void* const* d_in, const int* in_sizes, int n_in,
                              void* d_out, int out_size) {
    const float* x        = (const float*)d_in[0];
    const float* emb      = (const float*)d_in[3];
    const float* qkv_w    = (const float*)d_in[4];
    const float* qkv_b    = (const float*)d_in[5];
    const float* proj_w   = (const float*)d_in[6];
    const float* proj_b   = (const float*)d_in[7];
    const float* ff1_w    = (const float*)d_in[8];
    const float* ff1_b    = (const float*)d_in[9];
    const float* ff2_w    = (const float*)d_in[10];
    const float* ff2_b    = (const float*)d_in[11];
    const float* ada_w    = (const float*)d_in[12];
    const float* ada_b    = (const float*)d_in[13];
    const float* btab     = (const float*)d_in[14];
    float* xo = (float*)d_out;

    float *p_ada, *p_h, *p_qkv, *p_attn, *p_ff1;
    cudaGetSymbolAddress((void**)&p_ada,  g_ada);
    cudaGetSymbolAddress((void**)&p_h,    g_h);
    cudaGetSymbolAddress((void**)&p_qkv,  g_qkv);
    cudaGetSymbolAddress((void**)&p_attn, g_attn);
    cudaGetSymbolAddress((void**)&p_ff1,  g_ff1);

    const int NTOT = MROWS * C;
    copy_kernel<<<(NTOT + 255) / 256, 256>>>(xo, x, NTOT);

    for (int i = 0; i < 2; i++) {
        int shift = (i == 0) ? 0 : 4;
        const float* qw  = qkv_w  + (size_t)i * 1152 * C;
        const float* qb  = qkv_b  + (size_t)i * 1152;
        const float* pw  = proj_w + (size_t)i * C * C;
        const float* pb  = proj_b + (size_t)i * C;
        const float* f1w = ff1_w  + (size_t)i * FF * C;
        const float* f1b = ff1_b  + (size_t)i * FF;
        const float* f2w = ff2_w  + (size_t)i * C * FF;
        const float* f2b = ff2_b  + (size_t)i * C;
        const float* aw  = ada_w  + (size_t)i * 2304 * C;
        const float* ab  = ada_b  + (size_t)i * 2304;
        const float* bt  = btab   + (size_t)i * 225 * NHEAD;

        ada_kernel<<<dim3(2304 / 256, Bsz), 256>>>(emb, aw, ab, p_ada);
        ln_mod_kernel<<<MROWS, 128>>>(xo, p_ada, p_h, shift, 1, 384, 0);
        gemm_tf32<<<dim3(1152 / 128, MROWS / 128), 256>>>(p_h, qw, qb, p_qkv, 1152, C, 0);
        attn_kernel<<<dim3(512, NHEAD), 64>>>(p_qkv, bt, p_attn, shift);
        gemm_tf32<<<dim3(C / 128, MROWS / 128), 256>>>(p_attn, pw, pb, p_h, C, C, 0);
        resid_sa_kernel<<<(NTOT + 255) / 256, 256>>>(xo, p_h, p_ada, shift);
        ln_mod_kernel<<<MROWS, 128>>>(xo, p_ada, p_h, 0, 0, 1536, 1152);
        gemm_tf32<<<dim3(FF / 128, MROWS / 128), 256>>>(p_h, f1w, f1b, p_ff1, FF, C, 1);
        gemm_tf32<<<dim3(C / 128, MROWS / 128), 256>>>(p_ff1, f2w, f2b, p_h, C, FF, 0);
        resid_ff_kernel<<<(NTOT + 255) / 256, 256>>>(xo, p_h, p_ada);
    }
}

// round 9
// speedup vs baseline: 2.9299x; 1.1658x over previous
#include <cuda_runtime.h>
#include <cstdint>
#include <math.h>

#define Bsz   8
#define C     384
#define NHEAD 12
#define HD    32
#define FF    1536
#define MROWS 32768   // B * H * W = 8*64*64

// ---------------- scratch (device globals; no allocation) ----------------
__device__ float g_ada[Bsz * 2304];
__device__ float g_h[MROWS * C];
__device__ float g_qkv[(size_t)MROWS * 1152];
__device__ float g_attn[MROWS * C];
__device__ float g_ff1[(size_t)MROWS * FF];

// ---------------- copy x -> out ----------------
__global__ void copy_kernel(float* __restrict__ dst, const float* __restrict__ src, int n) {
    int i = blockIdx.x * blockDim.x + threadIdx.x;
    if (i < n) dst[i] = src[i];
}

// ---------------- adaLN ----------------
__global__ void ada_kernel(const float* __restrict__ emb, const float* __restrict__ ada_w,
                           const float* __restrict__ ada_b, float* __restrict__ ada_out) {
    int b = blockIdx.y;
    int j = blockIdx.x * blockDim.x + threadIdx.x;
    __shared__ float se[C];
    for (int k = threadIdx.x; k < C; k += blockDim.x) {
        float e = emb[b * C + k];
        se[k] = e / (1.0f + __expf(-e));
    }
    __syncthreads();
    const float* wrow = ada_w + (size_t)j * C;
    float s = ada_b[j];
#pragma unroll 4
    for (int k = 0; k < C; k++) s += se[k] * wrow[k];
    ada_out[b * 2304 + j] = s;
}

// ---------------- LayerNorm + modulate (+ optional window/shift gather) ----------------
__global__ void ln_mod_kernel(const float* __restrict__ x, const float* __restrict__ ada,
                              float* __restrict__ out, int shift, int windowed,
                              int sc_off, int sh_off) {
    int wrow = blockIdx.x;
    int tid = threadIdx.x;
    int b, srcrow;
    if (windowed) {
        int win = wrow >> 6, n = wrow & 63;
        b = win >> 6;
        int widx = win & 63;
        int wh = widx >> 3, wwi = widx & 7, ii = n >> 3, jj = n & 7;
        int r = (wh * 8 + ii + shift) & 63;
        int cc = (wwi * 8 + jj + shift) & 63;
        srcrow = b * 4096 + r * 64 + cc;
    } else {
        b = wrow >> 12;
        srcrow = wrow;
    }
    const float* xr = x + (size_t)srcrow * C;
    float v0 = xr[tid], v1 = xr[tid + 128], v2 = xr[tid + 256];
    float s = v0 + v1 + v2;
    float q = v0 * v0 + v1 * v1 + v2 * v2;
#pragma unroll
    for (int o = 16; o > 0; o >>= 1) {
        s += __shfl_down_sync(0xffffffffu, s, o);
        q += __shfl_down_sync(0xffffffffu, q, o);
    }
    __shared__ float rs[4], rq[4], mv[2];
    int wid = tid >> 5, lane = tid & 31;
    if (lane == 0) { rs[wid] = s; rq[wid] = q; }
    __syncthreads();
    if (tid == 0) {
        float S = rs[0] + rs[1] + rs[2] + rs[3];
        float Q = rq[0] + rq[1] + rq[2] + rq[3];
        float mean = S * (1.0f / C);
        float var = Q * (1.0f / C) - mean * mean;
        mv[0] = mean;
        mv[1] = rsqrtf(var + 1e-6f);
    }
    __syncthreads();
    float mean = mv[0], rstd = mv[1];
    const float* sc = ada + b * 2304 + sc_off;
    const float* sh = ada + b * 2304 + sh_off;
    float* orow = out + (size_t)wrow * C;
    orow[tid]       = (v0 - mean) * rstd * (1.0f + sc[tid])       + sh[tid];
    orow[tid + 128] = (v1 - mean) * rstd * (1.0f + sc[tid + 128]) + sh[tid + 128];
    orow[tid + 256] = (v2 - mean) * rstd * (1.0f + sc[tid + 256]) + sh[tid + 256];
}

// ================= tf32 tensor-core GEMM v3 =================
// C[m,n] = sum_k A[m,k]*W[n,k] + bias[n]; act=1 -> exact GELU.
// BM=256, BN=128, BK=32; 256 threads, 8 warps of 64x64; 3-stage cp.async; CTA swizzle.
#define TS 36            // smem row stride in floats (4*row+k mod 32 -> conflict-free)
#define A_STG (256 * TS) // floats per A stage
#define B_STG (128 * TS)
#define STG_FLOATS (A_STG + B_STG)
#define GEMM_SMEM (3 * STG_FLOATS * 4)

__device__ __forceinline__ void cpasync16(uint32_t dst, const void* src) {
    asm volatile("cp.async.cg.shared.global [%0], [%1], 16;" :: "r"(dst), "l"(src));
}
__device__ __forceinline__ void cp_commit() { asm volatile("cp.async.commit_group;"); }
__device__ __forceinline__ void cp_wait0() { asm volatile("cp.async.wait_group 0;"); }
__device__ __forceinline__ void cp_wait1() { asm volatile("cp.async.wait_group 1;"); }

__device__ __forceinline__ void mma_tf32(float* d, const uint32_t* a, const uint32_t* b) {
    asm volatile(
        "mma.sync.aligned.m16n8k8.row.col.f32.tf32.tf32.f32 "
        "{%0,%1,%2,%3}, {%4,%5,%6,%7}, {%8,%9}, {%0,%1,%2,%3};"
        : "+f"(d[0]), "+f"(d[1]), "+f"(d[2]), "+f"(d[3])
        : "r"(a[0]), "r"(a[1]), "r"(a[2]), "r"(a[3]), "r"(b[0]), "r"(b[1]));
}

__device__ __forceinline__ void g_load_stage(uint32_t sbase, const float* A, const float* W,
                                             int K, int kt, int bm, int bn, int tid) {
    int k0 = kt * 32;
#pragma unroll
    for (int j = 0; j < 12; j++) {
        int c = tid + j * 256;               // 0..3071
        if (c < 2048) {                       // A: 256 rows x 8 chunks
            int row = c >> 3, q = c & 7;
            cpasync16(sbase + (row * TS + q * 4) * 4,
                      A + (size_t)(bm + row) * K + k0 + q * 4);
        } else {                              // B: 128 rows x 8 chunks
            int c2 = c - 2048;
            int row = c2 >> 3, q = c2 & 7;
            cpasync16(sbase + (A_STG + row * TS + q * 4) * 4,
                      W + (size_t)(bn + row) * K + k0 + q * 4);
        }
    }
}

__global__ __launch_bounds__(256, 1) void gemm_tf32(const float* __restrict__ A,
                                                    const float* __restrict__ W,
                                                    const float* __restrict__ bias,
                                                    float* __restrict__ Cout,
                                                    int N, int K, int act) {
    extern __shared__ float smem[];
    uint32_t sb0 = (uint32_t)__cvta_generic_to_shared(smem);

    int tid = threadIdx.x;
    int warp = tid >> 5, lane = tid & 31;
    int grp = lane >> 2, qid = lane & 3;
    int wm = warp & 3, wn = warp >> 2;        // 4 x 2 warp grid
    int m_w = wm * 64, n_w = wn * 64;

    // CTA swizzle: group 8 M-blocks so a wave shares B columns & A rows in L2
    int NB = gridDim.x, MB = gridDim.y;
    int lin = blockIdx.y * NB + blockIdx.x;
    const int GM = 8;
    int gsz = GM * NB;
    int g = lin / gsz, rr = lin - g * gsz;
    int gm = min(GM, MB - g * GM);
    int mb = g * GM + rr % gm;
    int nb = rr / gm;
    int bm = mb * 256, bn = nb * 128;

    float acc[4][8][4];
#pragma unroll
    for (int i = 0; i < 4; i++)
#pragma unroll
        for (int j = 0; j < 8; j++)
#pragma unroll
            for (int r = 0; r < 4; r++) acc[i][j][r] = 0.0f;

    int nk = K / 32;
    g_load_stage(sb0, A, W, K, 0, bm, bn, tid); cp_commit();
    if (nk > 1) { g_load_stage(sb0 + STG_FLOATS * 4, A, W, K, 1, bm, bn, tid); cp_commit(); }

    for (int kt = 0; kt < nk; kt++) {
        if (kt + 1 < nk) cp_wait1(); else cp_wait0();
        __syncthreads();
        if (kt + 2 < nk) {
            g_load_stage(sb0 + ((kt + 2) % 3) * STG_FLOATS * 4, A, W, K, kt + 2, bm, bn, tid);
            cp_commit();
        }
        const uint32_t* Au = (const uint32_t*)(smem + (kt % 3) * STG_FLOATS);
        const uint32_t* Bu = Au + A_STG;
#pragma unroll
        for (int kk = 0; kk < 32; kk += 8) {
            uint32_t af[4][4], bf[8][2];
#pragma unroll
            for (int i = 0; i < 4; i++) {
                int m = m_w + 16 * i + grp;
                af[i][0] = Au[m * TS + kk + qid];
                af[i][1] = Au[(m + 8) * TS + kk + qid];
                af[i][2] = Au[m * TS + kk + qid + 4];
                af[i][3] = Au[(m + 8) * TS + kk + qid + 4];
            }
#pragma unroll
            for (int j = 0; j < 8; j++) {
                int nn = n_w + 8 * j + grp;
                bf[j][0] = Bu[nn * TS + kk + qid];
                bf[j][1] = Bu[nn * TS + kk + qid + 4];
            }
#pragma unroll
            for (int i = 0; i < 4; i++)
#pragma unroll
                for (int j = 0; j < 8; j++) mma_tf32(acc[i][j], af[i], bf[j]);
        }
    }

    // epilogue: direct float2 stores
#pragma unroll
    for (int i = 0; i < 4; i++) {
#pragma unroll
        for (int j = 0; j < 8; j++) {
            int row = bm + m_w + 16 * i + grp;
            int col = bn + n_w + 8 * j + 2 * qid;
            float b0 = __ldg(&bias[col]), b1 = __ldg(&bias[col + 1]);
            float v0 = acc[i][j][0] + b0, v1 = acc[i][j][1] + b1;
            float v2 = acc[i][j][2] + b0, v3 = acc[i][j][3] + b1;
            if (act == 1) {
                v0 = 0.5f * v0 * (1.0f + erff(v0 * 0.70710678118654752f));
                v1 = 0.5f * v1 * (1.0f + erff(v1 * 0.70710678118654752f));
                v2 = 0.5f * v2 * (1.0f + erff(v2 * 0.70710678118654752f));
                v3 = 0.5f * v3 * (1.0f + erff(v3 * 0.70710678118654752f));
            }
            *(float2*)&Cout[(size_t)row * N + col] = make_float2(v0, v1);
            *(float2*)&Cout[(size_t)(row + 8) * N + col] = make_float2(v2, v3);
        }
    }
}

// ---------------- window attention v2: two-pass online softmax ----------------
__device__ __forceinline__ int regid(int r) { return r < 56 ? 0 : (r < 60 ? 1 : 2); }

__global__ __launch_bounds__(64, 8) void attn_kernel(const float* __restrict__ qkv,
                                                     const float* __restrict__ bias_table,
                                                     float* __restrict__ out, int shift) {
    int win = blockIdx.x;
    int head = blockIdx.y;
    int n = threadIdx.x;
    __shared__ float4 ks4[64][8];
    __shared__ float4 vs4[64][8];
    __shared__ float bias_s[225];
    __shared__ int lab_s[64];

    size_t base = (size_t)win * 64 * 1152 + head * HD;
#pragma unroll
    for (int i = 0; i < 8; i++) {
        int idx = n + i * 64;
        int m = idx >> 3, dq = idx & 7;
        ks4[m][dq] = *(const float4*)&qkv[base + (size_t)m * 1152 + 384 + dq * 4];
        vs4[m][dq] = *(const float4*)&qkv[base + (size_t)m * 1152 + 768 + dq * 4];
    }
    float4 q4[8];
#pragma unroll
    for (int dq = 0; dq < 8; dq++) q4[dq] = *(const float4*)&qkv[base + (size_t)n * 1152 + dq * 4];
    for (int i = n; i < 225; i += 64) bias_s[i] = bias_table[i * NHEAD + head];

    int widx = win & 63;
    int wh = widx >> 3, wwi = widx & 7;
    {
        int ii = n >> 3, jj = n & 7;
        lab_s[n] = regid(wh * 8 + ii) * 3 + regid(wwi * 8 + jj);
    }
    __syncthreads();

    int ni = n >> 3, nj = n & 7;
    int labn = lab_s[n];

    // pass 1: online max + sum
    float mx = -1e30f, sm = 0.0f;
#pragma unroll 4
    for (int m = 0; m < 64; m++) {
        float acc = 0.0f;
#pragma unroll
        for (int dq = 0; dq < 8; dq++) {
            float4 k4 = ks4[m][dq];
            acc += q4[dq].x * k4.x + q4[dq].y * k4.y + q4[dq].z * k4.z + q4[dq].w * k4.w;
        }
        int mi = m >> 3, mj = m & 7;
        acc = acc * 0.17677669529663687f + bias_s[(ni - mi + 7) * 15 + (nj - mj + 7)];
        if (shift > 0 && lab_s[m] != labn) acc -= 100.0f;
        float nm = fmaxf(mx, acc);
        sm = sm * __expf(mx - nm) + __expf(acc - nm);
        mx = nm;
    }

    // pass 2: recompute scores, accumulate output
    float4 o4[8];
#pragma unroll
    for (int dq = 0; dq < 8; dq++) o4[dq] = make_float4(0.f, 0.f, 0.f, 0.f);
#pragma unroll 4
    for (int m = 0; m < 64; m++) {
        float acc = 0.0f;
#pragma unroll
        for (int dq = 0; dq < 8; dq++) {
            float4 k4 = ks4[m][dq];
            acc += q4[dq].x * k4.x + q4[dq].y * k4.y + q4[dq].z * k4.z + q4[dq].w * k4.w;
        }
        int mi = m >> 3, mj = m & 7;
        acc = acc * 0.17677669529663687f + bias_s[(ni - mi + 7) * 15 + (nj - mj + 7)];
        if (shift > 0 && lab_s[m] != labn) acc -= 100.0f;
        float p = __expf(acc - mx);
#pragma unroll
        for (int dq = 0; dq < 8; dq++) {
            float4 v4 = vs4[m][dq];
            o4[dq].x += p * v4.x; o4[dq].y += p * v4.y;
            o4[dq].z += p * v4.z; o4[dq].w += p * v4.w;
        }
    }
    float inv = 1.0f / sm;
    float* orow = out + (size_t)(win * 64 + n) * C + head * HD;
#pragma unroll
    for (int dq = 0; dq < 8; dq++) {
        float4 o = o4[dq];
        o.x *= inv; o.y *= inv; o.z *= inv; o.w *= inv;
        *(float4*)&orow[dq * 4] = o;
    }
}

// ---------------- residual scatter (SA path) ----------------
__global__ void resid_sa_kernel(float* __restrict__ x, const float* __restrict__ pout,
                                const float* __restrict__ ada, int shift) {
    int idx = blockIdx.x * blockDim.x + threadIdx.x;
    if (idx >= MROWS * C) return;
    int wrow = idx / C, c = idx - wrow * C;
    int win = wrow >> 6, n = wrow & 63;
    int b = win >> 6, widx = win & 63;
    int wh = widx >> 3, wwi = widx & 7, ii = n >> 3, jj = n & 7;
    int r = (wh * 8 + ii + shift) & 63;
    int cc = (wwi * 8 + jj + shift) & 63;
    size_t drow = (size_t)b * 4096 + r * 64 + cc;
    float g = ada[b * 2304 + 768 + c];
    x[drow * C + c] += g * pout[(size_t)wrow * C + c];
}

// ---------------- residual (FF path) ----------------
__global__ void resid_ff_kernel(float* __restrict__ x, const float* __restrict__ fout,
                                const float* __restrict__ ada) {
    int idx = blockIdx.x * blockDim.x + threadIdx.x;
    if (idx >= MROWS * C) return;
    int row = idx / C, c = idx - row * C;
    int b = row >> 12;
    x[idx] += ada[b * 2304 + 1920 + c] * fout[idx];
}

// ---------------- host ----------------
extern "C" void kernel_launch(void* const* d_in, const int* in_sizes, int n_in,
                              void* d_out, int out_size) {
    const float* x        = (const float*)d_in[0];
    const float* emb      = (const float*)d_in[3];
    const float* qkv_w    = (const float*)d_in[4];
    const float* qkv_b    = (const float*)d_in[5];
    const float* proj_w   = (const float*)d_in[6];
    const float* proj_b   = (const float*)d_in[7];
    const float* ff1_w    = (const float*)d_in[8];
    const float* ff1_b    = (const float*)d_in[9];
    const float* ff2_w    = (const float*)d_in[10];
    const float* ff2_b    = (const float*)d_in[11];
    const float* ada_w    = (const float*)d_in[12];
    const float* ada_b    = (const float*)d_in[13];
    const float* btab     = (const float*)d_in[14];
    float* xo = (float*)d_out;

    float *p_ada, *p_h, *p_qkv, *p_attn, *p_ff1;
    cudaGetSymbolAddress((void**)&p_ada,  g_ada);
    cudaGetSymbolAddress((void**)&p_h,    g_h);
    cudaGetSymbolAddress((void**)&p_qkv,  g_qkv);
    cudaGetSymbolAddress((void**)&p_attn, g_attn);
    cudaGetSymbolAddress((void**)&p_ff1,  g_ff1);

    static int smem_set = 0;
    if (!smem_set) {
        cudaFuncSetAttribute(gemm_tf32, cudaFuncAttributeMaxDynamicSharedMemorySize, GEMM_SMEM);
        smem_set = 1;
    }

    const int NTOT = MROWS * C;
    copy_kernel<<<(NTOT + 255) / 256, 256>>>(xo, x, NTOT);

    for (int i = 0; i < 2; i++) {
        int shift = (i == 0) ? 0 : 4;
        const float* qw  = qkv_w  + (size_t)i * 1152 * C;
        const float* qb  = qkv_b  + (size_t)i * 1152;
        const float* pw  = proj_w + (size_t)i * C * C;
        const float* pb  = proj_b + (size_t)i * C;
        const float* f1w = ff1_w  + (size_t)i * FF * C;
        const float* f1b = ff1_b  + (size_t)i * FF;
        const float* f2w = ff2_w  + (size_t)i * C * FF;
        const float* f2b = ff2_b  + (size_t)i * C;
        const float* aw  = ada_w  + (size_t)i * 2304 * C;
        const float* ab  = ada_b  + (size_t)i * 2304;
        const float* bt  = btab   + (size_t)i * 225 * NHEAD;

        ada_kernel<<<dim3(2304 / 256, Bsz), 256>>>(emb, aw, ab, p_ada);
        ln_mod_kernel<<<MROWS, 128>>>(xo, p_ada, p_h, shift, 1, 384, 0);
        gemm_tf32<<<dim3(1152 / 128, MROWS / 256), 256, GEMM_SMEM>>>(p_h, qw, qb, p_qkv, 1152, C, 0);
        attn_kernel<<<dim3(512, NHEAD), 64>>>(p_qkv, bt, p_attn, shift);
        gemm_tf32<<<dim3(C / 128, MROWS / 256), 256, GEMM_SMEM>>>(p_attn, pw, pb, p_h, C, C, 0);
        resid_sa_kernel<<<(NTOT + 255) / 256, 256>>>(xo, p_h, p_ada, shift);
        ln_mod_kernel<<<MROWS, 128>>>(xo, p_ada, p_h, 0, 0, 1536, 1152);
        gemm_tf32<<<dim3(FF / 128, MROWS / 256), 256, GEMM_SMEM>>>(p_h, f1w, f1b, p_ff1, FF, C, 1);
        gemm_tf32<<<dim3(C / 128, MROWS / 256), 256, GEMM_SMEM>>>(p_ff1, f2w, f2b, p_h, C, FF, 0);
        resid_ff_kernel<<<(NTOT + 255) / 256, 256>>>(xo, p_h, p_ada);
    }
}

// round 10
// speedup vs baseline: 3.0284x; 1.0336x over previous
#include <cuda_runtime.h>
#include <cstdint>
#include <math.h>

#define Bsz   8
#define C     384
#define NHEAD 12
#define HD    32
#define FF    1536
#define MROWS 32768   // B * H * W = 8*64*64

// ---------------- scratch (device globals; no allocation) ----------------
__device__ float g_ada[Bsz * 2304];
__device__ float g_h[MROWS * C];
__device__ float g_qkv[(size_t)MROWS * 1152];
__device__ float g_attn[MROWS * C];
__device__ float g_ff1[(size_t)MROWS * FF];

// ---------------- copy x -> out ----------------
__global__ void copy_kernel(float* __restrict__ dst, const float* __restrict__ src, int n) {
    int i = blockIdx.x * blockDim.x + threadIdx.x;
    if (i < n) dst[i] = src[i];
}

// ---------------- adaLN ----------------
__global__ void ada_kernel(const float* __restrict__ emb, const float* __restrict__ ada_w,
                           const float* __restrict__ ada_b, float* __restrict__ ada_out) {
    int b = blockIdx.y;
    int j = blockIdx.x * blockDim.x + threadIdx.x;
    __shared__ float se[C];
    for (int k = threadIdx.x; k < C; k += blockDim.x) {
        float e = emb[b * C + k];
        se[k] = e / (1.0f + __expf(-e));
    }
    __syncthreads();
    const float* wrow = ada_w + (size_t)j * C;
    float s = ada_b[j];
#pragma unroll 4
    for (int k = 0; k < C; k++) s += se[k] * wrow[k];
    ada_out[b * 2304 + j] = s;
}

// ---------------- LayerNorm + modulate (+ optional window/shift gather) ----------------
__global__ void ln_mod_kernel(const float* __restrict__ x, const float* __restrict__ ada,
                              float* __restrict__ out, int shift, int windowed,
                              int sc_off, int sh_off) {
    int wrow = blockIdx.x;
    int tid = threadIdx.x;
    int b, srcrow;
    if (windowed) {
        int win = wrow >> 6, n = wrow & 63;
        b = win >> 6;
        int widx = win & 63;
        int wh = widx >> 3, wwi = widx & 7, ii = n >> 3, jj = n & 7;
        int r = (wh * 8 + ii + shift) & 63;
        int cc = (wwi * 8 + jj + shift) & 63;
        srcrow = b * 4096 + r * 64 + cc;
    } else {
        b = wrow >> 12;
        srcrow = wrow;
    }
    const float* xr = x + (size_t)srcrow * C;
    float v0 = xr[tid], v1 = xr[tid + 128], v2 = xr[tid + 256];
    float s = v0 + v1 + v2;
    float q = v0 * v0 + v1 * v1 + v2 * v2;
#pragma unroll
    for (int o = 16; o > 0; o >>= 1) {
        s += __shfl_down_sync(0xffffffffu, s, o);
        q += __shfl_down_sync(0xffffffffu, q, o);
    }
    __shared__ float rs[4], rq[4], mv[2];
    int wid = tid >> 5, lane = tid & 31;
    if (lane == 0) { rs[wid] = s; rq[wid] = q; }
    __syncthreads();
    if (tid == 0) {
        float S = rs[0] + rs[1] + rs[2] + rs[3];
        float Q = rq[0] + rq[1] + rq[2] + rq[3];
        float mean = S * (1.0f / C);
        float var = Q * (1.0f / C) - mean * mean;
        mv[0] = mean;
        mv[1] = rsqrtf(var + 1e-6f);
    }
    __syncthreads();
    float mean = mv[0], rstd = mv[1];
    const float* sc = ada + b * 2304 + sc_off;
    const float* sh = ada + b * 2304 + sh_off;
    float* orow = out + (size_t)wrow * C;
    orow[tid]       = (v0 - mean) * rstd * (1.0f + sc[tid])       + sh[tid];
    orow[tid + 128] = (v1 - mean) * rstd * (1.0f + sc[tid + 128]) + sh[tid + 128];
    orow[tid + 256] = (v2 - mean) * rstd * (1.0f + sc[tid + 256]) + sh[tid + 256];
}

// ================= tf32 tensor-core GEMM v4 =================
// C[m,n] = sum_k A[m,k]*W[n,k] + bias[n]; act=1 -> exact GELU.
// BM=256, BN=128, BK=32; 256 threads, 8 warps of 64x64; 3-stage cp.async; CTA swizzle.
// k-permuted mma feeding: mma-col c maps to logical k = kk + (c<4 ? 2c : 2(c-4)+1),
// applied identically to A and B, so fragment pairs are contiguous -> LDS.64.
// TS=40 floats: per-half-warp bank = (8*grp + 2*qid) mod 32, all distinct -> conflict-free.
#define TS 40
#define A_STG (256 * TS)
#define B_STG (128 * TS)
#define STG_FLOATS (A_STG + B_STG)
#define GEMM_SMEM (3 * STG_FLOATS * 4)

__device__ __forceinline__ void cpasync16(uint32_t dst, const void* src) {
    asm volatile("cp.async.cg.shared.global [%0], [%1], 16;" :: "r"(dst), "l"(src));
}
__device__ __forceinline__ void cp_commit() { asm volatile("cp.async.commit_group;"); }
__device__ __forceinline__ void cp_wait0() { asm volatile("cp.async.wait_group 0;"); }
__device__ __forceinline__ void cp_wait1() { asm volatile("cp.async.wait_group 1;"); }

__device__ __forceinline__ void mma_tf32(float* d, const uint32_t* a, const uint32_t* b) {
    asm volatile(
        "mma.sync.aligned.m16n8k8.row.col.f32.tf32.tf32.f32 "
        "{%0,%1,%2,%3}, {%4,%5,%6,%7}, {%8,%9}, {%0,%1,%2,%3};"
        : "+f"(d[0]), "+f"(d[1]), "+f"(d[2]), "+f"(d[3])
        : "r"(a[0]), "r"(a[1]), "r"(a[2]), "r"(a[3]), "r"(b[0]), "r"(b[1]));
}

__device__ __forceinline__ void g_load_stage(uint32_t sbase, const float* A, const float* W,
                                             int K, int kt, int bm, int bn, int tid) {
    int k0 = kt * 32;
#pragma unroll
    for (int j = 0; j < 12; j++) {
        int c = tid + j * 256;               // 0..3071
        if (c < 2048) {                       // A: 256 rows x 8 chunks
            int row = c >> 3, q = c & 7;
            cpasync16(sbase + (row * TS + q * 4) * 4,
                      A + (size_t)(bm + row) * K + k0 + q * 4);
        } else {                              // B: 128 rows x 8 chunks
            int c2 = c - 2048;
            int row = c2 >> 3, q = c2 & 7;
            cpasync16(sbase + (A_STG + row * TS + q * 4) * 4,
                      W + (size_t)(bn + row) * K + k0 + q * 4);
        }
    }
}

__global__ __launch_bounds__(256, 1) void gemm_tf32(const float* __restrict__ A,
                                                    const float* __restrict__ W,
                                                    const float* __restrict__ bias,
                                                    float* __restrict__ Cout,
                                                    int N, int K, int act) {
    extern __shared__ float smem[];

    int tid = threadIdx.x;
    int warp = tid >> 5, lane = tid & 31;
    int grp = lane >> 2, qid = lane & 3;
    int wm = warp & 3, wn = warp >> 2;        // 4 x 2 warp grid
    int m_w = wm * 64, n_w = wn * 64;

    // CTA swizzle: group 8 M-blocks so a wave shares B columns & A rows in L2
    int NB = gridDim.x, MB = gridDim.y;
    int lin = blockIdx.y * NB + blockIdx.x;
    const int GM = 8;
    int gsz = GM * NB;
    int g = lin / gsz, rr = lin - g * gsz;
    int gm = min(GM, MB - g * GM);
    int mb = g * GM + rr % gm;
    int nb = rr / gm;
    int bm = mb * 256, bn = nb * 128;

    uint32_t sb0 = (uint32_t)__cvta_generic_to_shared(smem);

    float acc[4][8][4];
#pragma unroll
    for (int i = 0; i < 4; i++)
#pragma unroll
        for (int j = 0; j < 8; j++)
#pragma unroll
            for (int r = 0; r < 4; r++) acc[i][j][r] = 0.0f;

    int nk = K / 32;
    g_load_stage(sb0, A, W, K, 0, bm, bn, tid); cp_commit();
    if (nk > 1) { g_load_stage(sb0 + STG_FLOATS * 4, A, W, K, 1, bm, bn, tid); cp_commit(); }

    for (int kt = 0; kt < nk; kt++) {
        if (kt + 1 < nk) cp_wait1(); else cp_wait0();
        __syncthreads();
        if (kt + 2 < nk) {
            g_load_stage(sb0 + ((kt + 2) % 3) * STG_FLOATS * 4, A, W, K, kt + 2, bm, bn, tid);
            cp_commit();
        }
        const float* Sf = smem + (kt % 3) * STG_FLOATS;
#pragma unroll
        for (int kk = 0; kk < 32; kk += 8) {
            uint32_t af[4][4], bf[8][2];
#pragma unroll
            for (int i = 0; i < 4; i++) {
                int m = m_w + 16 * i + grp;
                uint2 fa  = *(const uint2*)&Sf[m * TS + kk + 2 * qid];
                uint2 fa8 = *(const uint2*)&Sf[(m + 8) * TS + kk + 2 * qid];
                af[i][0] = fa.x;  af[i][1] = fa8.x;
                af[i][2] = fa.y;  af[i][3] = fa8.y;
            }
#pragma unroll
            for (int j = 0; j < 8; j++) {
                int nn = n_w + 8 * j + grp;
                uint2 fb = *(const uint2*)&Sf[A_STG + nn * TS + kk + 2 * qid];
                bf[j][0] = fb.x;  bf[j][1] = fb.y;
            }
#pragma unroll
            for (int i = 0; i < 4; i++)
#pragma unroll
                for (int j = 0; j < 8; j++) mma_tf32(acc[i][j], af[i], bf[j]);
        }
    }

    // epilogue: direct float2 stores
#pragma unroll
    for (int i = 0; i < 4; i++) {
#pragma unroll
        for (int j = 0; j < 8; j++) {
            int row = bm + m_w + 16 * i + grp;
            int col = bn + n_w + 8 * j + 2 * qid;
            float b0 = __ldg(&bias[col]), b1 = __ldg(&bias[col + 1]);
            float v0 = acc[i][j][0] + b0, v1 = acc[i][j][1] + b1;
            float v2 = acc[i][j][2] + b0, v3 = acc[i][j][3] + b1;
            if (act == 1) {
                v0 = 0.5f * v0 * (1.0f + erff(v0 * 0.70710678118654752f));
                v1 = 0.5f * v1 * (1.0f + erff(v1 * 0.70710678118654752f));
                v2 = 0.5f * v2 * (1.0f + erff(v2 * 0.70710678118654752f));
                v3 = 0.5f * v3 * (1.0f + erff(v3 * 0.70710678118654752f));
            }
            *(float2*)&Cout[(size_t)row * N + col] = make_float2(v0, v1);
            *(float2*)&Cout[(size_t)(row + 8) * N + col] = make_float2(v2, v3);
        }
    }
}

// ---------------- window attention v2: two-pass online softmax ----------------
__device__ __forceinline__ int regid(int r) { return r < 56 ? 0 : (r < 60 ? 1 : 2); }

__global__ __launch_bounds__(64, 8) void attn_kernel(const float* __restrict__ qkv,
                                                     const float* __restrict__ bias_table,
                                                     float* __restrict__ out, int shift) {
    int win = blockIdx.x;
    int head = blockIdx.y;
    int n = threadIdx.x;
    __shared__ float4 ks4[64][8];
    __shared__ float4 vs4[64][8];
    __shared__ float bias_s[225];
    __shared__ int lab_s[64];

    size_t base = (size_t)win * 64 * 1152 + head * HD;
#pragma unroll
    for (int i = 0; i < 8; i++) {
        int idx = n + i * 64;
        int m = idx >> 3, dq = idx & 7;
        ks4[m][dq] = *(const float4*)&qkv[base + (size_t)m * 1152 + 384 + dq * 4];
        vs4[m][dq] = *(const float4*)&qkv[base + (size_t)m * 1152 + 768 + dq * 4];
    }
    float4 q4[8];
#pragma unroll
    for (int dq = 0; dq < 8; dq++) q4[dq] = *(const float4*)&qkv[base + (size_t)n * 1152 + dq * 4];
    for (int i = n; i < 225; i += 64) bias_s[i] = bias_table[i * NHEAD + head];

    int widx = win & 63;
    int wh = widx >> 3, wwi = widx & 7;
    {
        int ii = n >> 3, jj = n & 7;
        lab_s[n] = regid(wh * 8 + ii) * 3 + regid(wwi * 8 + jj);
    }
    __syncthreads();

    int ni = n >> 3, nj = n & 7;
    int labn = lab_s[n];

    float mx = -1e30f, sm = 0.0f;
#pragma unroll 4
    for (int m = 0; m < 64; m++) {
        float acc = 0.0f;
#pragma unroll
        for (int dq = 0; dq < 8; dq++) {
            float4 k4 = ks4[m][dq];
            acc += q4[dq].x * k4.x + q4[dq].y * k4.y + q4[dq].z * k4.z + q4[dq].w * k4.w;
        }
        int mi = m >> 3, mj = m & 7;
        acc = acc * 0.17677669529663687f + bias_s[(ni - mi + 7) * 15 + (nj - mj + 7)];
        if (shift > 0 && lab_s[m] != labn) acc -= 100.0f;
        float nm = fmaxf(mx, acc);
        sm = sm * __expf(mx - nm) + __expf(acc - nm);
        mx = nm;
    }

    float4 o4[8];
#pragma unroll
    for (int dq = 0; dq < 8; dq++) o4[dq] = make_float4(0.f, 0.f, 0.f, 0.f);
#pragma unroll 4
    for (int m = 0; m < 64; m++) {
        float acc = 0.0f;
#pragma unroll
        for (int dq = 0; dq < 8; dq++) {
            float4 k4 = ks4[m][dq];
            acc += q4[dq].x * k4.x + q4[dq].y * k4.y + q4[dq].z * k4.z + q4[dq].w * k4.w;
        }
        int mi = m >> 3, mj = m & 7;
        acc = acc * 0.17677669529663687f + bias_s[(ni - mi + 7) * 15 + (nj - mj + 7)];
        if (shift > 0 && lab_s[m] != labn) acc -= 100.0f;
        float p = __expf(acc - mx);
#pragma unroll
        for (int dq = 0; dq < 8; dq++) {
            float4 v4 = vs4[m][dq];
            o4[dq].x += p * v4.x; o4[dq].y += p * v4.y;
            o4[dq].z += p * v4.z; o4[dq].w += p * v4.w;
        }
    }
    float inv = 1.0f / sm;
    float* orow = out + (size_t)(win * 64 + n) * C + head * HD;
#pragma unroll
    for (int dq = 0; dq < 8; dq++) {
        float4 o = o4[dq];
        o.x *= inv; o.y *= inv; o.z *= inv; o.w *= inv;
        *(float4*)&orow[dq * 4] = o;
    }
}

// ---------------- residual scatter (SA path) ----------------
__global__ void resid_sa_kernel(float* __restrict__ x, const float* __restrict__ pout,
                                const float* __restrict__ ada, int shift) {
    int idx = blockIdx.x * blockDim.x + threadIdx.x;
    if (idx >= MROWS * C) return;
    int wrow = idx / C, c = idx - wrow * C;
    int win = wrow >> 6, n = wrow & 63;
    int b = win >> 6, widx = win & 63;
    int wh = widx >> 3, wwi = widx & 7, ii = n >> 3, jj = n & 7;
    int r = (wh * 8 + ii + shift) & 63;
    int cc = (wwi * 8 + jj + shift) & 63;
    size_t drow = (size_t)b * 4096 + r * 64 + cc;
    float g = ada[b * 2304 + 768 + c];
    x[drow * C + c] += g * pout[(size_t)wrow * C + c];
}

// ---------------- residual (FF path) ----------------
__global__ void resid_ff_kernel(float* __restrict__ x, const float* __restrict__ fout,
                                const float* __restrict__ ada) {
    int idx = blockIdx.x * blockDim.x + threadIdx.x;
    if (idx >= MROWS * C) return;
    int row = idx / C, c = idx - row * C;
    int b = row >> 12;
    x[idx] += ada[b * 2304 + 1920 + c] * fout[idx];
}

// ---------------- host ----------------
extern "C" void kernel_launch(void* const* d_in, const int* in_sizes, int n_in,
                              void* d_out, int out_size) {
    const float* x        = (const float*)d_in[0];
    const float* emb      = (const float*)d_in[3];
    const float* qkv_w    = (const float*)d_in[4];
    const float* qkv_b    = (const float*)d_in[5];
    const float* proj_w   = (const float*)d_in[6];
    const float* proj_b   = (const float*)d_in[7];
    const float* ff1_w    = (const float*)d_in[8];
    const float* ff1_b    = (const float*)d_in[9];
    const float* ff2_w    = (const float*)d_in[10];
    const float* ff2_b    = (const float*)d_in[11];
    const float* ada_w    = (const float*)d_in[12];
    const float* ada_b    = (const float*)d_in[13];
    const float* btab     = (const float*)d_in[14];
    float* xo = (float*)d_out;

    float *p_ada, *p_h, *p_qkv, *p_attn, *p_ff1;
    cudaGetSymbolAddress((void**)&p_ada,  g_ada);
    cudaGetSymbolAddress((void**)&p_h,    g_h);
    cudaGetSymbolAddress((void**)&p_qkv,  g_qkv);
    cudaGetSymbolAddress((void**)&p_attn, g_attn);
    cudaGetSymbolAddress((void**)&p_ff1,  g_ff1);

    static int smem_set = 0;
    if (!smem_set) {
        cudaFuncSetAttribute(gemm_tf32, cudaFuncAttributeMaxDynamicSharedMemorySize, GEMM_SMEM);
        smem_set = 1;
    }

    const int NTOT = MROWS * C;
    copy_kernel<<<(NTOT + 255) / 256, 256>>>(xo, x, NTOT);

    for (int i = 0; i < 2; i++) {
        int shift = (i == 0) ? 0 : 4;
        const float* qw  = qkv_w  + (size_t)i * 1152 * C;
        const float* qb  = qkv_b  + (size_t)i * 1152;
        const float* pw  = proj_w + (size_t)i * C * C;
        const float* pb  = proj_b + (size_t)i * C;
        const float* f1w = ff1_w  + (size_t)i * FF * C;
        const float* f1b = ff1_b  + (size_t)i * FF;
        const float* f2w = ff2_w  + (size_t)i * C * FF;
        const float* f2b = ff2_b  + (size_t)i * C;
        const float* aw  = ada_w  + (size_t)i * 2304 * C;
        const float* ab  = ada_b  + (size_t)i * 2304;
        const float* bt  = btab   + (size_t)i * 225 * NHEAD;

        ada_kernel<<<dim3(2304 / 256, Bsz), 256>>>(emb, aw, ab, p_ada);
        ln_mod_kernel<<<MROWS, 128>>>(xo, p_ada, p_h, shift, 1, 384, 0);
        gemm_tf32<<<dim3(1152 / 128, MROWS / 256), 256, GEMM_SMEM>>>(p_h, qw, qb, p_qkv, 1152, C, 0);
        attn_kernel<<<dim3(512, NHEAD), 64>>>(p_qkv, bt, p_attn, shift);
        gemm_tf32<<<dim3(C / 128, MROWS / 256), 256, GEMM_SMEM>>>(p_attn, pw, pb, p_h, C, C, 0);
        resid_sa_kernel<<<(NTOT + 255) / 256, 256>>>(xo, p_h, p_ada, shift);
        ln_mod_kernel<<<MROWS, 128>>>(xo, p_ada, p_h, 0, 0, 1536, 1152);
        gemm_tf32<<<dim3(FF / 128, MROWS / 256), 256, GEMM_SMEM>>>(p_h, f1w, f1b, p_ff1, FF, C, 1);
        gemm_tf32<<<dim3(C / 128, MROWS / 256), 256, GEMM_SMEM>>>(p_ff1, f2w, f2b, p_h, C, FF, 0);
        resid_ff_kernel<<<(NTOT + 255) / 256, 256>>>(xo, p_h, p_ada);
    }
}

// round 11
// speedup vs baseline: 3.1026x; 1.0245x over previous
#include <cuda_runtime.h>
#include <cstdint>
#include <math.h>

#define Bsz   8
#define C     384
#define NHEAD 12
#define HD    32
#define FF    1536
#define MROWS 32768   // B * H * W = 8*64*64

// ---------------- scratch (device globals; no allocation) ----------------
__device__ float g_ada[Bsz * 2304];
__device__ float g_h[MROWS * C];
__device__ float g_qkv[(size_t)MROWS * 1152];
__device__ float g_attn[MROWS * C];
__device__ float g_ff1[(size_t)MROWS * FF];

// ---------------- copy x -> out ----------------
__global__ void copy_kernel(float* __restrict__ dst, const float* __restrict__ src, int n) {
    int i = blockIdx.x * blockDim.x + threadIdx.x;
    if (i < n) dst[i] = src[i];
}

// ---------------- adaLN ----------------
__global__ void ada_kernel(const float* __restrict__ emb, const float* __restrict__ ada_w,
                           const float* __restrict__ ada_b, float* __restrict__ ada_out) {
    int b = blockIdx.y;
    int j = blockIdx.x * blockDim.x + threadIdx.x;
    __shared__ float se[C];
    for (int k = threadIdx.x; k < C; k += blockDim.x) {
        float e = emb[b * C + k];
        se[k] = e / (1.0f + __expf(-e));
    }
    __syncthreads();
    const float* wrow = ada_w + (size_t)j * C;
    float s = ada_b[j];
#pragma unroll 4
    for (int k = 0; k < C; k++) s += se[k] * wrow[k];
    ada_out[b * 2304 + j] = s;
}

// ---------------- LayerNorm + modulate (+ optional window/shift gather) ----------------
__global__ void ln_mod_kernel(const float* __restrict__ x, const float* __restrict__ ada,
                              float* __restrict__ out, int shift, int windowed,
                              int sc_off, int sh_off) {
    int wrow = blockIdx.x;
    int tid = threadIdx.x;
    int b, srcrow;
    if (windowed) {
        int win = wrow >> 6, n = wrow & 63;
        b = win >> 6;
        int widx = win & 63;
        int wh = widx >> 3, wwi = widx & 7, ii = n >> 3, jj = n & 7;
        int r = (wh * 8 + ii + shift) & 63;
        int cc = (wwi * 8 + jj + shift) & 63;
        srcrow = b * 4096 + r * 64 + cc;
    } else {
        b = wrow >> 12;
        srcrow = wrow;
    }
    const float* xr = x + (size_t)srcrow * C;
    float v0 = xr[tid], v1 = xr[tid + 128], v2 = xr[tid + 256];
    float s = v0 + v1 + v2;
    float q = v0 * v0 + v1 * v1 + v2 * v2;
#pragma unroll
    for (int o = 16; o > 0; o >>= 1) {
        s += __shfl_down_sync(0xffffffffu, s, o);
        q += __shfl_down_sync(0xffffffffu, q, o);
    }
    __shared__ float rs[4], rq[4], mv[2];
    int wid = tid >> 5, lane = tid & 31;
    if (lane == 0) { rs[wid] = s; rq[wid] = q; }
    __syncthreads();
    if (tid == 0) {
        float S = rs[0] + rs[1] + rs[2] + rs[3];
        float Q = rq[0] + rq[1] + rq[2] + rq[3];
        float mean = S * (1.0f / C);
        float var = Q * (1.0f / C) - mean * mean;
        mv[0] = mean;
        mv[1] = rsqrtf(var + 1e-6f);
    }
    __syncthreads();
    float mean = mv[0], rstd = mv[1];
    const float* sc = ada + b * 2304 + sc_off;
    const float* sh = ada + b * 2304 + sh_off;
    float* orow = out + (size_t)wrow * C;
    orow[tid]       = (v0 - mean) * rstd * (1.0f + sc[tid])       + sh[tid];
    orow[tid + 128] = (v1 - mean) * rstd * (1.0f + sc[tid + 128]) + sh[tid + 128];
    orow[tid + 256] = (v2 - mean) * rstd * (1.0f + sc[tid + 256]) + sh[tid + 256];
}

// ================= tf32 tensor-core GEMM v5 =================
// C[m,n] = sum_k A[m,k]*W[n,k] + bias[n]; act=1 -> exact GELU.
// BM=256, BN=128, BK=32; 512 threads / 16 warps (4x4), warp tile 64x32.
// 3-stage cp.async pipeline; CTA swizzle; k-permuted LDS.64 fragment loads.
#define TS 40
#define A_STG (256 * TS)
#define B_STG (128 * TS)
#define STG_FLOATS (A_STG + B_STG)
#define GEMM_SMEM (3 * STG_FLOATS * 4)

__device__ __forceinline__ void cpasync16(uint32_t dst, const void* src) {
    asm volatile("cp.async.cg.shared.global [%0], [%1], 16;" :: "r"(dst), "l"(src));
}
__device__ __forceinline__ void cp_commit() { asm volatile("cp.async.commit_group;"); }
__device__ __forceinline__ void cp_wait0() { asm volatile("cp.async.wait_group 0;"); }
__device__ __forceinline__ void cp_wait1() { asm volatile("cp.async.wait_group 1;"); }

__device__ __forceinline__ void mma_tf32(float* d, const uint32_t* a, const uint32_t* b) {
    asm volatile(
        "mma.sync.aligned.m16n8k8.row.col.f32.tf32.tf32.f32 "
        "{%0,%1,%2,%3}, {%4,%5,%6,%7}, {%8,%9}, {%0,%1,%2,%3};"
        : "+f"(d[0]), "+f"(d[1]), "+f"(d[2]), "+f"(d[3])
        : "r"(a[0]), "r"(a[1]), "r"(a[2]), "r"(a[3]), "r"(b[0]), "r"(b[1]));
}

__device__ __forceinline__ void g_load_stage(uint32_t sbase, const float* A, const float* W,
                                             int K, int kt, int bm, int bn, int tid) {
    int k0 = kt * 32;
#pragma unroll
    for (int j = 0; j < 6; j++) {
        int c = tid + j * 512;                // 0..3071
        if (c < 2048) {                       // A: 256 rows x 8 chunks
            int row = c >> 3, q = c & 7;
            cpasync16(sbase + (row * TS + q * 4) * 4,
                      A + (size_t)(bm + row) * K + k0 + q * 4);
        } else {                              // B: 128 rows x 8 chunks
            int c2 = c - 2048;
            int row = c2 >> 3, q = c2 & 7;
            cpasync16(sbase + (A_STG + row * TS + q * 4) * 4,
                      W + (size_t)(bn + row) * K + k0 + q * 4);
        }
    }
}

__global__ __launch_bounds__(512, 1) void gemm_tf32(const float* __restrict__ A,
                                                    const float* __restrict__ W,
                                                    const float* __restrict__ bias,
                                                    float* __restrict__ Cout,
                                                    int N, int K, int act) {
    extern __shared__ float smem[];

    int tid = threadIdx.x;
    int warp = tid >> 5, lane = tid & 31;
    int grp = lane >> 2, qid = lane & 3;
    int wm = warp & 3, wn = warp >> 2;        // 4 x 4 warp grid
    int m_w = wm * 64, n_w = wn * 32;

    // CTA swizzle: group 8 M-blocks so a wave shares B columns & A rows in L2
    int NB = gridDim.x, MB = gridDim.y;
    int lin = blockIdx.y * NB + blockIdx.x;
    const int GM = 8;
    int gsz = GM * NB;
    int g = lin / gsz, rr = lin - g * gsz;
    int gm = min(GM, MB - g * GM);
    int mb = g * GM + rr % gm;
    int nb = rr / gm;
    int bm = mb * 256, bn = nb * 128;

    uint32_t sb0 = (uint32_t)__cvta_generic_to_shared(smem);

    float acc[4][4][4];
#pragma unroll
    for (int i = 0; i < 4; i++)
#pragma unroll
        for (int j = 0; j < 4; j++)
#pragma unroll
            for (int r = 0; r < 4; r++) acc[i][j][r] = 0.0f;

    int nk = K / 32;
    g_load_stage(sb0, A, W, K, 0, bm, bn, tid); cp_commit();
    if (nk > 1) { g_load_stage(sb0 + STG_FLOATS * 4, A, W, K, 1, bm, bn, tid); cp_commit(); }

    for (int kt = 0; kt < nk; kt++) {
        if (kt + 1 < nk) cp_wait1(); else cp_wait0();
        __syncthreads();
        if (kt + 2 < nk) {
            g_load_stage(sb0 + ((kt + 2) % 3) * STG_FLOATS * 4, A, W, K, kt + 2, bm, bn, tid);
            cp_commit();
        }
        const float* Sf = smem + (kt % 3) * STG_FLOATS;
#pragma unroll
        for (int kk = 0; kk < 32; kk += 8) {
            uint32_t af[4][4], bf[4][2];
#pragma unroll
            for (int i = 0; i < 4; i++) {
                int m = m_w + 16 * i + grp;
                uint2 fa  = *(const uint2*)&Sf[m * TS + kk + 2 * qid];
                uint2 fa8 = *(const uint2*)&Sf[(m + 8) * TS + kk + 2 * qid];
                af[i][0] = fa.x;  af[i][1] = fa8.x;
                af[i][2] = fa.y;  af[i][3] = fa8.y;
            }
#pragma unroll
            for (int j = 0; j < 4; j++) {
                int nn = n_w + 8 * j + grp;
                uint2 fb = *(const uint2*)&Sf[A_STG + nn * TS + kk + 2 * qid];
                bf[j][0] = fb.x;  bf[j][1] = fb.y;
            }
#pragma unroll
            for (int i = 0; i < 4; i++)
#pragma unroll
                for (int j = 0; j < 4; j++) mma_tf32(acc[i][j], af[i], bf[j]);
        }
    }

    // epilogue: direct float2 stores
#pragma unroll
    for (int i = 0; i < 4; i++) {
#pragma unroll
        for (int j = 0; j < 4; j++) {
            int row = bm + m_w + 16 * i + grp;
            int col = bn + n_w + 8 * j + 2 * qid;
            float b0 = __ldg(&bias[col]), b1 = __ldg(&bias[col + 1]);
            float v0 = acc[i][j][0] + b0, v1 = acc[i][j][1] + b1;
            float v2 = acc[i][j][2] + b0, v3 = acc[i][j][3] + b1;
            if (act == 1) {
                v0 = 0.5f * v0 * (1.0f + erff(v0 * 0.70710678118654752f));
                v1 = 0.5f * v1 * (1.0f + erff(v1 * 0.70710678118654752f));
                v2 = 0.5f * v2 * (1.0f + erff(v2 * 0.70710678118654752f));
                v3 = 0.5f * v3 * (1.0f + erff(v3 * 0.70710678118654752f));
            }
            *(float2*)&Cout[(size_t)row * N + col] = make_float2(v0, v1);
            *(float2*)&Cout[(size_t)(row + 8) * N + col] = make_float2(v2, v3);
        }
    }
}

// ---------------- window attention v2: two-pass online softmax ----------------
__device__ __forceinline__ int regid(int r) { return r < 56 ? 0 : (r < 60 ? 1 : 2); }

__global__ __launch_bounds__(64, 8) void attn_kernel(const float* __restrict__ qkv,
                                                     const float* __restrict__ bias_table,
                                                     float* __restrict__ out, int shift) {
    int win = blockIdx.x;
    int head = blockIdx.y;
    int n = threadIdx.x;
    __shared__ float4 ks4[64][8];
    __shared__ float4 vs4[64][8];
    __shared__ float bias_s[225];
    __shared__ int lab_s[64];

    size_t base = (size_t)win * 64 * 1152 + head * HD;
#pragma unroll
    for (int i = 0; i < 8; i++) {
        int idx = n + i * 64;
        int m = idx >> 3, dq = idx & 7;
        ks4[m][dq] = *(const float4*)&qkv[base + (size_t)m * 1152 + 384 + dq * 4];
        vs4[m][dq] = *(const float4*)&qkv[base + (size_t)m * 1152 + 768 + dq * 4];
    }
    float4 q4[8];
#pragma unroll
    for (int dq = 0; dq < 8; dq++) q4[dq] = *(const float4*)&qkv[base + (size_t)n * 1152 + dq * 4];
    for (int i = n; i < 225; i += 64) bias_s[i] = bias_table[i * NHEAD + head];

    int widx = win & 63;
    int wh = widx >> 3, wwi = widx & 7;
    {
        int ii = n >> 3, jj = n & 7;
        lab_s[n] = regid(wh * 8 + ii) * 3 + regid(wwi * 8 + jj);
    }
    __syncthreads();

    int ni = n >> 3, nj = n & 7;
    int labn = lab_s[n];

    float mx = -1e30f, sm = 0.0f;
#pragma unroll 4
    for (int m = 0; m < 64; m++) {
        float acc = 0.0f;
#pragma unroll
        for (int dq = 0; dq < 8; dq++) {
            float4 k4 = ks4[m][dq];
            acc += q4[dq].x * k4.x + q4[dq].y * k4.y + q4[dq].z * k4.z + q4[dq].w * k4.w;
        }
        int mi = m >> 3, mj = m & 7;
        acc = acc * 0.17677669529663687f + bias_s[(ni - mi + 7) * 15 + (nj - mj + 7)];
        if (shift > 0 && lab_s[m] != labn) acc -= 100.0f;
        float nm = fmaxf(mx, acc);
        sm = sm * __expf(mx - nm) + __expf(acc - nm);
        mx = nm;
    }

    float4 o4[8];
#pragma unroll
    for (int dq = 0; dq < 8; dq++) o4[dq] = make_float4(0.f, 0.f, 0.f, 0.f);
#pragma unroll 4
    for (int m = 0; m < 64; m++) {
        float acc = 0.0f;
#pragma unroll
        for (int dq = 0; dq < 8; dq++) {
            float4 k4 = ks4[m][dq];
            acc += q4[dq].x * k4.x + q4[dq].y * k4.y + q4[dq].z * k4.z + q4[dq].w * k4.w;
        }
        int mi = m >> 3, mj = m & 7;
        acc = acc * 0.17677669529663687f + bias_s[(ni - mi + 7) * 15 + (nj - mj + 7)];
        if (shift > 0 && lab_s[m] != labn) acc -= 100.0f;
        float p = __expf(acc - mx);
#pragma unroll
        for (int dq = 0; dq < 8; dq++) {
            float4 v4 = vs4[m][dq];
            o4[dq].x += p * v4.x; o4[dq].y += p * v4.y;
            o4[dq].z += p * v4.z; o4[dq].w += p * v4.w;
        }
    }
    float inv = 1.0f / sm;
    float* orow = out + (size_t)(win * 64 + n) * C + head * HD;
#pragma unroll
    for (int dq = 0; dq < 8; dq++) {
        float4 o = o4[dq];
        o.x *= inv; o.y *= inv; o.z *= inv; o.w *= inv;
        *(float4*)&orow[dq * 4] = o;
    }
}

// ---------------- residual scatter (SA path), float4 ----------------
__global__ void resid_sa_kernel(float* __restrict__ x, const float* __restrict__ pout,
                                const float* __restrict__ ada, int shift) {
    int idx = blockIdx.x * blockDim.x + threadIdx.x;   // over NTOT/4
    if (idx >= MROWS * C / 4) return;
    int wrow = idx / (C / 4), cq = idx - wrow * (C / 4);
    int c = cq * 4;
    int win = wrow >> 6, n = wrow & 63;
    int b = win >> 6, widx = win & 63;
    int wh = widx >> 3, wwi = widx & 7, ii = n >> 3, jj = n & 7;
    int r = (wh * 8 + ii + shift) & 63;
    int cc = (wwi * 8 + jj + shift) & 63;
    size_t drow = (size_t)b * 4096 + r * 64 + cc;
    float4 g = *(const float4*)&ada[b * 2304 + 768 + c];
    float4 p = *(const float4*)&pout[(size_t)wrow * C + c];
    float4* xp = (float4*)&x[drow * C + c];
    float4 xv = *xp;
    xv.x += g.x * p.x; xv.y += g.y * p.y; xv.z += g.z * p.z; xv.w += g.w * p.w;
    *xp = xv;
}

// ---------------- residual (FF path), float4 ----------------
__global__ void resid_ff_kernel(float* __restrict__ x, const float* __restrict__ fout,
                                const float* __restrict__ ada) {
    int idx = blockIdx.x * blockDim.x + threadIdx.x;   // over NTOT/4
    if (idx >= MROWS * C / 4) return;
    int row = idx / (C / 4), cq = idx - row * (C / 4);
    int c = cq * 4;
    int b = row >> 12;
    float4 g = *(const float4*)&ada[b * 2304 + 1920 + c];
    float4 f = *(const float4*)&fout[(size_t)row * C + c];
    float4* xp = (float4*)&x[(size_t)row * C + c];
    float4 xv = *xp;
    xv.x += g.x * f.x; xv.y += g.y * f.y; xv.z += g.z * f.z; xv.w += g.w * f.w;
    *xp = xv;
}

// ---------------- host ----------------
extern "C" void kernel_launch(void* const* d_in, const int* in_sizes, int n_in,
                              void* d_out, int out_size) {
    const float* x        = (const float*)d_in[0];
    const float* emb      = (const float*)d_in[3];
    const float* qkv_w    = (const float*)d_in[4];
    const float* qkv_b    = (const float*)d_in[5];
    const float* proj_w   = (const float*)d_in[6];
    const float* proj_b   = (const float*)d_in[7];
    const float* ff1_w    = (const float*)d_in[8];
    const float* ff1_b    = (const float*)d_in[9];
    const float* ff2_w    = (const float*)d_in[10];
    const float* ff2_b    = (const float*)d_in[11];
    const float* ada_w    = (const float*)d_in[12];
    const float* ada_b    = (const float*)d_in[13];
    const float* btab     = (const float*)d_in[14];
    float* xo = (float*)d_out;

    float *p_ada, *p_h, *p_qkv, *p_attn, *p_ff1;
    cudaGetSymbolAddress((void**)&p_ada,  g_ada);
    cudaGetSymbolAddress((void**)&p_h,    g_h);
    cudaGetSymbolAddress((void**)&p_qkv,  g_qkv);
    cudaGetSymbolAddress((void**)&p_attn, g_attn);
    cudaGetSymbolAddress((void**)&p_ff1,  g_ff1);

    static int smem_set = 0;
    if (!smem_set) {
        cudaFuncSetAttribute(gemm_tf32, cudaFuncAttributeMaxDynamicSharedMemorySize, GEMM_SMEM);
        smem_set = 1;
    }

    const int NTOT = MROWS * C;
    const int NQ = NTOT / 4;
    copy_kernel<<<(NTOT + 255) / 256, 256>>>(xo, x, NTOT);

    for (int i = 0; i < 2; i++) {
        int shift = (i == 0) ? 0 : 4;
        const float* qw  = qkv_w  + (size_t)i * 1152 * C;
        const float* qb  = qkv_b  + (size_t)i * 1152;
        const float* pw  = proj_w + (size_t)i * C * C;
        const float* pb  = proj_b + (size_t)i * C;
        const float* f1w = ff1_w  + (size_t)i * FF * C;
        const float* f1b = ff1_b  + (size_t)i * FF;
        const float* f2w = ff2_w  + (size_t)i * C * FF;
        const float* f2b = ff2_b  + (size_t)i * C;
        const float* aw  = ada_w  + (size_t)i * 2304 * C;
        const float* ab  = ada_b  + (size_t)i * 2304;
        const float* bt  = btab   + (size_t)i * 225 * NHEAD;

        ada_kernel<<<dim3(2304 / 256, Bsz), 256>>>(emb, aw, ab, p_ada);
        ln_mod_kernel<<<MROWS, 128>>>(xo, p_ada, p_h, shift, 1, 384, 0);
        gemm_tf32<<<dim3(1152 / 128, MROWS / 256), 512, GEMM_SMEM>>>(p_h, qw, qb, p_qkv, 1152, C, 0);
        attn_kernel<<<dim3(512, NHEAD), 64>>>(p_qkv, bt, p_attn, shift);
        gemm_tf32<<<dim3(C / 128, MROWS / 256), 512, GEMM_SMEM>>>(p_attn, pw, pb, p_h, C, C, 0);
        resid_sa_kernel<<<(NQ + 255) / 256, 256>>>(xo, p_h, p_ada, shift);
        ln_mod_kernel<<<MROWS, 128>>>(xo, p_ada, p_h, 0, 0, 1536, 1152);
        gemm_tf32<<<dim3(FF / 128, MROWS / 256), 512, GEMM_SMEM>>>(p_h, f1w, f1b, p_ff1, FF, C, 1);
        gemm_tf32<<<dim3(C / 128, MROWS / 256), 512, GEMM_SMEM>>>(p_ff1, f2w, f2b, p_h, C, FF, 0);
        resid_ff_kernel<<<(NQ + 255) / 256, 256>>>(xo, p_h, p_ada);
    }
}